// round 1
// baseline (speedup 1.0000x reference)
#include <cuda_runtime.h>
#include <cstdint>

#define N_NODES 100000
#define N_EDGES 1600000
#define D_IN    128
#define D_HID   128
#define D_OUT   70
#define D_OUT_P 72   // padded stride for layer-2 (16B-aligned rows)

// ---------------- scratch (static device memory; no allocation) -------------
__device__ __align__(256) int   g_deg [N_NODES];
__device__ __align__(256) float g_dinv[N_NODES];
__device__ __align__(256) float g_y1  [(size_t)N_NODES * D_HID];
__device__ __align__(256) float g_acc1[(size_t)N_NODES * D_HID];
__device__ __align__(256) float g_h   [(size_t)N_NODES * D_HID];
__device__ __align__(256) float g_y2  [(size_t)N_NODES * D_OUT_P];
__device__ __align__(256) float g_acc2[(size_t)N_NODES * D_OUT_P];
__device__ int g_is64;

// ---------------- edge-index width detection (int32 vs int64) ---------------
__global__ void detect_k(const void* ei) {
    if (threadIdx.x == 0 && blockIdx.x == 0) {
        const int* p = (const int*)ei;
        int is64 = 1;
        for (int i = 0; i < 1000; i++) {
            if (p[2 * i + 1] != 0) { is64 = 0; break; }
        }
        g_is64 = is64;
    }
}

__device__ __forceinline__ int load_idx(const void* ei, long long i, int is64) {
    return is64 ? (int)(((const long long*)ei)[i]) : ((const int*)ei)[i];
}

// ---------------- degree / normalization ------------------------------------
__global__ void zero_deg_k() {
    int i = blockIdx.x * blockDim.x + threadIdx.x;
    if (i < N_NODES) g_deg[i] = 0;
}

__global__ void count_k(const void* __restrict__ ei) {
    int e = blockIdx.x * blockDim.x + threadIdx.x;
    if (e >= N_EDGES) return;
    int is64 = g_is64;
    int dst = load_idx(ei, (long long)N_EDGES + e, is64);
    atomicAdd(&g_deg[dst], 1);
}

__global__ void dinv_k() {
    int i = blockIdx.x * blockDim.x + threadIdx.x;
    if (i < N_NODES) g_dinv[i] = rsqrtf((float)(g_deg[i] + 1)); // +1 self-loop
}

// ---------------- GEMM 1: y = dinv .* (x @ W1), 128x128 ---------------------
// BM=64, BN=128, BK=32, 128 threads, per-thread 8x8 tile.
__global__ void __launch_bounds__(128) gemm1_k(const float* __restrict__ A,
                                               const float* __restrict__ W) {
    __shared__ float xs[32][64];    // transposed: xs[k][m]
    __shared__ float ws[32][128];   // ws[k][n]
    int tid = threadIdx.x;
    int tx = tid & 15, ty = tid >> 4;
    int r0 = blockIdx.x * 64;
    float acc[8][8] = {};
    for (int k0 = 0; k0 < 128; k0 += 32) {
        #pragma unroll
        for (int i = 0; i < 4; i++) {
            int l = tid + i * 128;          // 0..511 float4 slots
            int row = l >> 3, q = l & 7;
            float4 v = make_float4(0.f, 0.f, 0.f, 0.f);
            int gr = r0 + row;
            if (gr < N_NODES) v = *(const float4*)(A + (size_t)gr * 128 + k0 + q * 4);
            xs[q * 4 + 0][row] = v.x; xs[q * 4 + 1][row] = v.y;
            xs[q * 4 + 2][row] = v.z; xs[q * 4 + 3][row] = v.w;
        }
        #pragma unroll
        for (int i = 0; i < 8; i++) {
            int l = tid + i * 128;          // 0..1023 float4 slots
            int kr = l >> 5, q = l & 31;
            *(float4*)(&ws[kr][q * 4]) =
                *(const float4*)(W + (size_t)(k0 + kr) * 128 + q * 4);
        }
        __syncthreads();
        #pragma unroll
        for (int k = 0; k < 32; k++) {
            float a[8], b[8];
            *(float4*)(a)     = *(float4*)(&xs[k][ty * 8]);
            *(float4*)(a + 4) = *(float4*)(&xs[k][ty * 8 + 4]);
            *(float4*)(b)     = *(float4*)(&ws[k][tx * 8]);
            *(float4*)(b + 4) = *(float4*)(&ws[k][tx * 8 + 4]);
            #pragma unroll
            for (int i = 0; i < 8; i++)
                #pragma unroll
                for (int j = 0; j < 8; j++)
                    acc[i][j] = fmaf(a[i], b[j], acc[i][j]);
        }
        __syncthreads();
    }
    #pragma unroll
    for (int i = 0; i < 8; i++) {
        int gr = r0 + ty * 8 + i;
        if (gr >= N_NODES) break;
        float s = g_dinv[gr];
        float4 v0 = make_float4(acc[i][0] * s, acc[i][1] * s, acc[i][2] * s, acc[i][3] * s);
        float4 v1 = make_float4(acc[i][4] * s, acc[i][5] * s, acc[i][6] * s, acc[i][7] * s);
        size_t o = (size_t)gr * 128 + tx * 8;
        *(float4*)(g_y1 + o)       = v0;  *(float4*)(g_y1 + o + 4)   = v1;
        *(float4*)(g_acc1 + o)     = v0;  *(float4*)(g_acc1 + o + 4) = v1;  // self-loop init
    }
}

// ---------------- GEMM 2: y2 = dinv .* (h @ W2), 128x70 (padded to 72) ------
// BM=128, BN=72, BK=32, 288 threads (ty=tid/18 -> 8 rows, tx=tid%18 -> 4 cols)
__global__ void __launch_bounds__(288) gemm2_k(const float* __restrict__ W2) {
    __shared__ float xs[32][128];   // transposed
    __shared__ float ws[32][72];
    int tid = threadIdx.x;
    int tx = tid % 18, ty = tid / 18;
    int r0 = blockIdx.x * 128;
    float acc[8][4] = {};
    for (int k0 = 0; k0 < 128; k0 += 32) {
        for (int l = tid; l < 1024; l += 288) {      // 128x32 floats = 1024 float4
            int row = l >> 3, q = l & 7;
            float4 v = make_float4(0.f, 0.f, 0.f, 0.f);
            int gr = r0 + row;
            if (gr < N_NODES) v = *(const float4*)(g_h + (size_t)gr * 128 + k0 + q * 4);
            xs[q * 4 + 0][row] = v.x; xs[q * 4 + 1][row] = v.y;
            xs[q * 4 + 2][row] = v.z; xs[q * 4 + 3][row] = v.w;
        }
        #pragma unroll
        for (int i = 0; i < 8; i++) {                // 32x72 = 2304 scalars = 8*288
            int l = tid + i * 288;
            int kr = l / 72, n = l % 72;
            ws[kr][n] = (n < D_OUT) ? W2[(size_t)(k0 + kr) * D_OUT + n] : 0.f;
        }
        __syncthreads();
        #pragma unroll
        for (int k = 0; k < 32; k++) {
            float a[8], b[4];
            *(float4*)(a)     = *(float4*)(&xs[k][ty * 8]);
            *(float4*)(a + 4) = *(float4*)(&xs[k][ty * 8 + 4]);
            *(float4*)(b)     = *(float4*)(&ws[k][tx * 4]);
            #pragma unroll
            for (int i = 0; i < 8; i++)
                #pragma unroll
                for (int j = 0; j < 4; j++)
                    acc[i][j] = fmaf(a[i], b[j], acc[i][j]);
        }
        __syncthreads();
    }
    #pragma unroll
    for (int i = 0; i < 8; i++) {
        int gr = r0 + ty * 8 + i;
        if (gr >= N_NODES) break;
        float s = g_dinv[gr];
        float4 v = make_float4(acc[i][0] * s, acc[i][1] * s, acc[i][2] * s, acc[i][3] * s);
        size_t o = (size_t)gr * D_OUT_P + tx * 4;
        *(float4*)(g_y2 + o)   = v;
        *(float4*)(g_acc2 + o) = v;    // self-loop init
    }
}

// ---------------- edge scatter: acc[dst] += y[src] (vector atomics) ---------
template <int CH, int STRIDE>
__device__ __forceinline__ void scatter_body(const void* __restrict__ ei,
                                             const float* __restrict__ y,
                                             float* __restrict__ acc) {
    long long gid = (long long)blockIdx.x * blockDim.x + threadIdx.x;
    if (gid >= (long long)N_EDGES * CH) return;
    int e = (int)(gid / CH);
    int c = (int)(gid % CH);
    int is64 = g_is64;
    int src = load_idx(ei, e, is64);
    int dst = load_idx(ei, (long long)N_EDGES + e, is64);
    float4 v = *(const float4*)(y + (size_t)src * STRIDE + c * 4);
    float4* p = (float4*)(acc + (size_t)dst * STRIDE + c * 4);
    asm volatile("red.global.add.v4.f32 [%0], {%1,%2,%3,%4};"
                 :: "l"(p), "f"(v.x), "f"(v.y), "f"(v.z), "f"(v.w) : "memory");
}

__global__ void __launch_bounds__(256) scatter1_k(const void* __restrict__ ei) {
    scatter_body<32, 128>(ei, g_y1, g_acc1);
}
__global__ void __launch_bounds__(256) scatter2_k(const void* __restrict__ ei) {
    scatter_body<18, D_OUT_P>(ei, g_y2, g_acc2);
}

// ---------------- layer-1 epilogue: h = relu(dinv.*acc1 + b1) ---------------
__global__ void relu_k(const float* __restrict__ b1) {
    long long gid = (long long)blockIdx.x * blockDim.x + threadIdx.x;
    if (gid >= (long long)N_NODES * 32) return;
    int i = (int)(gid >> 5);
    int c = (int)(gid & 31);
    float s = g_dinv[i];
    float4 a = *(const float4*)(g_acc1 + (size_t)i * 128 + c * 4);
    float4 b = *(const float4*)(b1 + c * 4);
    float4 h;
    h.x = fmaxf(0.f, fmaf(s, a.x, b.x));
    h.y = fmaxf(0.f, fmaf(s, a.y, b.y));
    h.z = fmaxf(0.f, fmaf(s, a.z, b.z));
    h.w = fmaxf(0.f, fmaf(s, a.w, b.w));
    *(float4*)(g_h + (size_t)i * 128 + c * 4) = h;
}

// ---------------- layer-2 epilogue: out = dinv.*acc2 + b2 -------------------
__global__ void final_k(const float* __restrict__ b2, float* __restrict__ out) {
    long long gid = (long long)blockIdx.x * blockDim.x + threadIdx.x;
    if (gid >= (long long)N_NODES * D_OUT) return;
    int i = (int)(gid / D_OUT);
    int c = (int)(gid % D_OUT);
    out[gid] = fmaf(g_dinv[i], g_acc2[(size_t)i * D_OUT_P + c], b2[c]);
}

// ---------------- launch -----------------------------------------------------
extern "C" void kernel_launch(void* const* d_in, const int* in_sizes, int n_in,
                              void* d_out, int out_size) {
    const float* x  = (const float*)d_in[0];
    const void*  ei = d_in[1];              // int32 or int64, detected on device
    const float* W1 = (const float*)d_in[2];
    const float* b1 = (const float*)d_in[3];
    const float* W2 = (const float*)d_in[4];
    const float* b2 = (const float*)d_in[5];
    float* out = (float*)d_out;

    detect_k<<<1, 32>>>(ei);
    zero_deg_k<<<(N_NODES + 255) / 256, 256>>>();
    count_k<<<(N_EDGES + 255) / 256, 256>>>(ei);
    dinv_k<<<(N_NODES + 255) / 256, 256>>>();

    gemm1_k<<<(N_NODES + 63) / 64, 128>>>(x, W1);
    scatter1_k<<<(int)(((long long)N_EDGES * 32 + 255) / 256), 256>>>(ei);
    relu_k<<<(int)(((long long)N_NODES * 32 + 255) / 256), 256>>>(b1);

    gemm2_k<<<(N_NODES + 127) / 128, 288>>>(W2);
    scatter2_k<<<(int)(((long long)N_EDGES * 18 + 255) / 256), 256>>>(ei);
    final_k<<<(int)(((long long)N_NODES * D_OUT + 255) / 256), 256>>>(b2, out);
}

// round 2
// speedup vs baseline: 1.6808x; 1.6808x over previous
#include <cuda_runtime.h>
#include <cstdint>

#define N_NODES 100000
#define N_EDGES 1600000
#define D_IN    128
#define D_HID   128
#define D_OUT   70
#define D_OUT_P 72   // padded stride for layer-2 intermediates

// ---------------- scratch (static device memory; no allocation) -------------
__device__ __align__(256) int   g_deg   [N_NODES];
__device__ __align__(256) float g_dinv  [N_NODES];
__device__ __align__(256) int   g_rowptr[N_NODES + 1];
__device__ __align__(256) int   g_cursor[N_NODES];
__device__ __align__(256) int   g_incl  [N_NODES];
__device__ __align__(256) int   g_bsum  [128];
__device__ __align__(256) int   g_boff  [128];
__device__ __align__(256) int   g_nbr   [N_EDGES];
__device__ __align__(256) float g_y1    [(size_t)N_NODES * D_HID];
__device__ __align__(256) float g_h     [(size_t)N_NODES * D_HID];
__device__ __align__(256) float g_y2    [(size_t)N_NODES * D_OUT_P];
__device__ int g_is64;

// ---------------- edge-index width detection (int32 vs int64) ---------------
__global__ void detect_k(const void* ei) {
    if (threadIdx.x == 0 && blockIdx.x == 0) {
        const int* p = (const int*)ei;
        int is64 = 1;
        for (int i = 0; i < 1000; i++) {
            if (p[2 * i + 1] != 0) { is64 = 0; break; }
        }
        g_is64 = is64;
    }
}

__device__ __forceinline__ int load_idx(const void* ei, long long i, int is64) {
    return is64 ? (int)(((const long long*)ei)[i]) : ((const int*)ei)[i];
}

// ---------------- degree / normalization ------------------------------------
__global__ void zero_deg_k() {
    int i = blockIdx.x * blockDim.x + threadIdx.x;
    if (i < N_NODES) g_deg[i] = 0;
}

__global__ void count_k(const void* __restrict__ ei) {
    int e = blockIdx.x * blockDim.x + threadIdx.x;
    if (e >= N_EDGES) return;
    int dst = load_idx(ei, (long long)N_EDGES + e, g_is64);
    atomicAdd(&g_deg[dst], 1);
}

__global__ void dinv_k() {
    int i = blockIdx.x * blockDim.x + threadIdx.x;
    if (i < N_NODES) g_dinv[i] = rsqrtf((float)(g_deg[i] + 1)); // +1 self-loop
}

// ---------------- CSR build: hierarchical exclusive scan of deg --------------
// scan1: 98 blocks x 1024 threads, inclusive block scans
__global__ void __launch_bounds__(1024) scan1_k() {
    __shared__ int s[1024];
    int t = threadIdx.x;
    int i = blockIdx.x * 1024 + t;
    s[t] = (i < N_NODES) ? g_deg[i] : 0;
    __syncthreads();
    #pragma unroll
    for (int off = 1; off < 1024; off <<= 1) {
        int v = (t >= off) ? s[t - off] : 0;
        __syncthreads();
        s[t] += v;
        __syncthreads();
    }
    if (i < N_NODES) g_incl[i] = s[t];
    if (t == 1023) g_bsum[blockIdx.x] = s[1023];
}

// scan2: single block scans the per-block sums -> exclusive block offsets
__global__ void __launch_bounds__(128) scan2_k(int nblocks) {
    __shared__ int s[128];
    int t = threadIdx.x;
    int v0 = (t < nblocks) ? g_bsum[t] : 0;
    s[t] = v0;
    __syncthreads();
    #pragma unroll
    for (int off = 1; off < 128; off <<= 1) {
        int v = (t >= off) ? s[t - off] : 0;
        __syncthreads();
        s[t] += v;
        __syncthreads();
    }
    if (t < nblocks) g_boff[t] = s[t] - v0;   // exclusive
}

// scan3: produce rowptr and per-node fill cursors
__global__ void scan3_k() {
    int i = blockIdx.x * blockDim.x + threadIdx.x;
    if (i >= N_NODES) return;
    int incl = g_incl[i] + g_boff[i >> 10];
    g_rowptr[i + 1] = incl;
    g_cursor[i] = incl - g_deg[i];
    if (i == 0) g_rowptr[0] = 0;
}

__global__ void fill_k(const void* __restrict__ ei) {
    int e = blockIdx.x * blockDim.x + threadIdx.x;
    if (e >= N_EDGES) return;
    int is64 = g_is64;
    int src = load_idx(ei, e, is64);
    int dst = load_idx(ei, (long long)N_EDGES + e, is64);
    int pos = atomicAdd(&g_cursor[dst], 1);
    g_nbr[pos] = src;
}

// ---------------- GEMM 1: y1 = dinv .* (x @ W1), 128x128 --------------------
__global__ void __launch_bounds__(128) gemm1_k(const float* __restrict__ A,
                                               const float* __restrict__ W) {
    __shared__ float xs[32][64];
    __shared__ float ws[32][128];
    int tid = threadIdx.x;
    int tx = tid & 15, ty = tid >> 4;
    int r0 = blockIdx.x * 64;
    float acc[8][8] = {};
    for (int k0 = 0; k0 < 128; k0 += 32) {
        #pragma unroll
        for (int i = 0; i < 4; i++) {
            int l = tid + i * 128;
            int row = l >> 3, q = l & 7;
            float4 v = make_float4(0.f, 0.f, 0.f, 0.f);
            int gr = r0 + row;
            if (gr < N_NODES) v = *(const float4*)(A + (size_t)gr * 128 + k0 + q * 4);
            xs[q * 4 + 0][row] = v.x; xs[q * 4 + 1][row] = v.y;
            xs[q * 4 + 2][row] = v.z; xs[q * 4 + 3][row] = v.w;
        }
        #pragma unroll
        for (int i = 0; i < 8; i++) {
            int l = tid + i * 128;
            int kr = l >> 5, q = l & 31;
            *(float4*)(&ws[kr][q * 4]) =
                *(const float4*)(W + (size_t)(k0 + kr) * 128 + q * 4);
        }
        __syncthreads();
        #pragma unroll
        for (int k = 0; k < 32; k++) {
            float a[8], b[8];
            *(float4*)(a)     = *(float4*)(&xs[k][ty * 8]);
            *(float4*)(a + 4) = *(float4*)(&xs[k][ty * 8 + 4]);
            *(float4*)(b)     = *(float4*)(&ws[k][tx * 8]);
            *(float4*)(b + 4) = *(float4*)(&ws[k][tx * 8 + 4]);
            #pragma unroll
            for (int i = 0; i < 8; i++)
                #pragma unroll
                for (int j = 0; j < 8; j++)
                    acc[i][j] = fmaf(a[i], b[j], acc[i][j]);
        }
        __syncthreads();
    }
    #pragma unroll
    for (int i = 0; i < 8; i++) {
        int gr = r0 + ty * 8 + i;
        if (gr >= N_NODES) break;
        float s = g_dinv[gr];
        float4 v0 = make_float4(acc[i][0] * s, acc[i][1] * s, acc[i][2] * s, acc[i][3] * s);
        float4 v1 = make_float4(acc[i][4] * s, acc[i][5] * s, acc[i][6] * s, acc[i][7] * s);
        size_t o = (size_t)gr * 128 + tx * 8;
        *(float4*)(g_y1 + o)     = v0;
        *(float4*)(g_y1 + o + 4) = v1;
    }
}

// ---------------- GEMM 2: y2 = dinv .* (h @ W2), 128x70 (stride 72) ---------
__global__ void __launch_bounds__(288) gemm2_k(const float* __restrict__ W2) {
    __shared__ float xs[32][128];
    __shared__ float ws[32][72];
    int tid = threadIdx.x;
    int tx = tid % 18, ty = tid / 18;
    int r0 = blockIdx.x * 128;
    float acc[8][4] = {};
    for (int k0 = 0; k0 < 128; k0 += 32) {
        for (int l = tid; l < 1024; l += 288) {
            int row = l >> 3, q = l & 7;
            float4 v = make_float4(0.f, 0.f, 0.f, 0.f);
            int gr = r0 + row;
            if (gr < N_NODES) v = *(const float4*)(g_h + (size_t)gr * 128 + k0 + q * 4);
            xs[q * 4 + 0][row] = v.x; xs[q * 4 + 1][row] = v.y;
            xs[q * 4 + 2][row] = v.z; xs[q * 4 + 3][row] = v.w;
        }
        #pragma unroll
        for (int i = 0; i < 8; i++) {
            int l = tid + i * 288;
            int kr = l / 72, n = l % 72;
            ws[kr][n] = (n < D_OUT) ? W2[(size_t)(k0 + kr) * D_OUT + n] : 0.f;
        }
        __syncthreads();
        #pragma unroll
        for (int k = 0; k < 32; k++) {
            float a[8], b[4];
            *(float4*)(a)     = *(float4*)(&xs[k][ty * 8]);
            *(float4*)(a + 4) = *(float4*)(&xs[k][ty * 8 + 4]);
            *(float4*)(b)     = *(float4*)(&ws[k][tx * 4]);
            #pragma unroll
            for (int i = 0; i < 8; i++)
                #pragma unroll
                for (int j = 0; j < 4; j++)
                    acc[i][j] = fmaf(a[i], b[j], acc[i][j]);
        }
        __syncthreads();
    }
    #pragma unroll
    for (int i = 0; i < 8; i++) {
        int gr = r0 + ty * 8 + i;
        if (gr >= N_NODES) break;
        float s = g_dinv[gr];
        float4 v = make_float4(acc[i][0] * s, acc[i][1] * s, acc[i][2] * s, acc[i][3] * s);
        *(float4*)(g_y2 + (size_t)gr * D_OUT_P + tx * 4) = v;
    }
}

// ---------------- gather 1: h = relu(dinv .* (Σ_nbr y1 + y1_self) + b1) -----
// one warp per node; lane l owns columns [4l, 4l+4)
__global__ void __launch_bounds__(256) gather1_k(const float* __restrict__ b1) {
    int w = (blockIdx.x * 256 + threadIdx.x) >> 5;
    int lane = threadIdx.x & 31;
    if (w >= N_NODES) return;
    int start = g_rowptr[w], end = g_rowptr[w + 1];
    float4 a = *(const float4*)(g_y1 + (size_t)w * 128 + lane * 4);  // self loop
    for (int base = start; base < end; base += 32) {
        int idx = base + lane;
        int s = (idx < end) ? g_nbr[idx] : 0;
        int cnt = min(32, end - base);
        for (int j = 0; j < cnt; j++) {
            int sj = __shfl_sync(0xffffffffu, s, j);
            float4 v = *(const float4*)(g_y1 + (size_t)sj * 128 + lane * 4);
            a.x += v.x; a.y += v.y; a.z += v.z; a.w += v.w;
        }
    }
    float d = g_dinv[w];
    float4 bb = *(const float4*)(b1 + lane * 4);
    float4 h;
    h.x = fmaxf(0.f, fmaf(d, a.x, bb.x));
    h.y = fmaxf(0.f, fmaf(d, a.y, bb.y));
    h.z = fmaxf(0.f, fmaf(d, a.z, bb.z));
    h.w = fmaxf(0.f, fmaf(d, a.w, bb.w));
    *(float4*)(g_h + (size_t)w * 128 + lane * 4) = h;
}

// ---------------- gather 2: out = dinv .* (Σ_nbr y2 + y2_self) + b2 ---------
// one warp per node; lanes 0..17 own 4 columns each (cols 68..71 padding)
__global__ void __launch_bounds__(256) gather2_k(const float* __restrict__ b2,
                                                 float* __restrict__ out) {
    int w = (blockIdx.x * 256 + threadIdx.x) >> 5;
    int lane = threadIdx.x & 31;
    if (w >= N_NODES) return;
    int start = g_rowptr[w], end = g_rowptr[w + 1];
    float4 a = make_float4(0.f, 0.f, 0.f, 0.f);
    bool act = lane < 18;
    if (act) a = *(const float4*)(g_y2 + (size_t)w * D_OUT_P + lane * 4);
    for (int base = start; base < end; base += 32) {
        int idx = base + lane;
        int s = (idx < end) ? g_nbr[idx] : 0;
        int cnt = min(32, end - base);
        for (int j = 0; j < cnt; j++) {
            int sj = __shfl_sync(0xffffffffu, s, j);
            if (act) {
                float4 v = *(const float4*)(g_y2 + (size_t)sj * D_OUT_P + lane * 4);
                a.x += v.x; a.y += v.y; a.z += v.z; a.w += v.w;
            }
        }
    }
    if (act) {
        float d = g_dinv[w];
        int c = lane * 4;
        float* o = out + (size_t)w * D_OUT + c;
        float2 r0 = make_float2(fmaf(d, a.x, b2[c]), fmaf(d, a.y, b2[c + 1]));
        *(float2*)o = r0;                              // rows are 8B aligned
        if (lane < 17) {
            float2 r1 = make_float2(fmaf(d, a.z, b2[c + 2]), fmaf(d, a.w, b2[c + 3]));
            *(float2*)(o + 2) = r1;
        }
    }
}

// ---------------- launch -----------------------------------------------------
extern "C" void kernel_launch(void* const* d_in, const int* in_sizes, int n_in,
                              void* d_out, int out_size) {
    const float* x  = (const float*)d_in[0];
    const void*  ei = d_in[1];
    const float* W1 = (const float*)d_in[2];
    const float* b1 = (const float*)d_in[3];
    const float* W2 = (const float*)d_in[4];
    const float* b2 = (const float*)d_in[5];
    float* out = (float*)d_out;

    const int nscan = (N_NODES + 1023) / 1024;   // 98

    detect_k<<<1, 32>>>(ei);
    zero_deg_k<<<(N_NODES + 255) / 256, 256>>>();
    count_k<<<(N_EDGES + 255) / 256, 256>>>(ei);
    dinv_k<<<(N_NODES + 255) / 256, 256>>>();

    scan1_k<<<nscan, 1024>>>();
    scan2_k<<<1, 128>>>(nscan);
    scan3_k<<<(N_NODES + 255) / 256, 256>>>();
    fill_k<<<(N_EDGES + 255) / 256, 256>>>(ei);

    gemm1_k<<<(N_NODES + 63) / 64, 128>>>(x, W1);
    gather1_k<<<(N_NODES * 32 + 255) / 256, 256>>>(b1);

    gemm2_k<<<(N_NODES + 127) / 128, 288>>>(W2);
    gather2_k<<<(N_NODES * 32 + 255) / 256, 256>>>(b2, out);
}

// round 3
// speedup vs baseline: 1.8257x; 1.0862x over previous
#include <cuda_runtime.h>
#include <mma.h>
#include <cstdint>

using namespace nvcuda;

#define N_NODES 100000
#define N_EDGES 1600000
#define D_IN    128
#define D_HID   128
#define D_OUT   70
#define D_OUT_P 72   // padded stride for layer-2 intermediates

// ---------------- scratch (static device memory; no allocation) -------------
__device__ __align__(256) int   g_deg   [N_NODES];
__device__ __align__(256) float g_dinv  [N_NODES];
__device__ __align__(256) int   g_rowptr[N_NODES + 1];
__device__ __align__(256) int   g_cursor[N_NODES];
__device__ __align__(256) int   g_incl  [N_NODES];
__device__ __align__(256) int   g_bsum  [128];
__device__ __align__(256) int   g_boff  [128];
__device__ __align__(256) int   g_nbr   [N_EDGES];
__device__ __align__(256) float g_y1    [(size_t)N_NODES * D_HID];
__device__ __align__(256) float g_h     [(size_t)N_NODES * D_HID];
__device__ __align__(256) float g_y2    [(size_t)N_NODES * D_OUT_P];
__device__ int g_is64;

// ---------------- edge-index width detection (int32 vs int64) ---------------
__global__ void detect_k(const void* ei) {
    if (threadIdx.x == 0 && blockIdx.x == 0) {
        const int* p = (const int*)ei;
        int is64 = 1;
        for (int i = 0; i < 1000; i++) {
            if (p[2 * i + 1] != 0) { is64 = 0; break; }
        }
        g_is64 = is64;
    }
}

__device__ __forceinline__ int load_idx(const void* ei, long long i, int is64) {
    return is64 ? (int)(((const long long*)ei)[i]) : ((const int*)ei)[i];
}

// ---------------- degree / normalization ------------------------------------
__global__ void zero_deg_k() {
    int i = blockIdx.x * blockDim.x + threadIdx.x;
    if (i < N_NODES) g_deg[i] = 0;
}

__global__ void count_k(const void* __restrict__ ei) {
    int e = blockIdx.x * blockDim.x + threadIdx.x;
    if (e >= N_EDGES) return;
    int dst = load_idx(ei, (long long)N_EDGES + e, g_is64);
    atomicAdd(&g_deg[dst], 1);
}

__global__ void dinv_k() {
    int i = blockIdx.x * blockDim.x + threadIdx.x;
    if (i < N_NODES) g_dinv[i] = rsqrtf((float)(g_deg[i] + 1)); // +1 self-loop
}

// ---------------- CSR build: hierarchical exclusive scan of deg --------------
__global__ void __launch_bounds__(1024) scan1_k() {
    __shared__ int s[1024];
    int t = threadIdx.x;
    int i = blockIdx.x * 1024 + t;
    s[t] = (i < N_NODES) ? g_deg[i] : 0;
    __syncthreads();
    #pragma unroll
    for (int off = 1; off < 1024; off <<= 1) {
        int v = (t >= off) ? s[t - off] : 0;
        __syncthreads();
        s[t] += v;
        __syncthreads();
    }
    if (i < N_NODES) g_incl[i] = s[t];
    if (t == 1023) g_bsum[blockIdx.x] = s[1023];
}

__global__ void __launch_bounds__(128) scan2_k(int nblocks) {
    __shared__ int s[128];
    int t = threadIdx.x;
    int v0 = (t < nblocks) ? g_bsum[t] : 0;
    s[t] = v0;
    __syncthreads();
    #pragma unroll
    for (int off = 1; off < 128; off <<= 1) {
        int v = (t >= off) ? s[t - off] : 0;
        __syncthreads();
        s[t] += v;
        __syncthreads();
    }
    if (t < nblocks) g_boff[t] = s[t] - v0;   // exclusive
}

__global__ void scan3_k() {
    int i = blockIdx.x * blockDim.x + threadIdx.x;
    if (i >= N_NODES) return;
    int incl = g_incl[i] + g_boff[i >> 10];
    g_rowptr[i + 1] = incl;
    g_cursor[i] = incl - g_deg[i];
    if (i == 0) g_rowptr[0] = 0;
}

__global__ void fill_k(const void* __restrict__ ei) {
    int e = blockIdx.x * blockDim.x + threadIdx.x;
    if (e >= N_EDGES) return;
    int is64 = g_is64;
    int src = load_idx(ei, e, is64);
    int dst = load_idx(ei, (long long)N_EDGES + e, is64);
    int pos = atomicAdd(&g_cursor[dst], 1);
    g_nbr[pos] = src;
}

// ---------------- GEMM 1 (tf32 WMMA): y1 = dinv .* (x @ W1), 128x128 --------
// BM=64, BN=128, 8 warps (2x4). K=128 fully staged in smem, 1 sync.
#define LDA 132
__global__ void __launch_bounds__(256) gemm1_k(const float* __restrict__ A,
                                               const float* __restrict__ W) {
    extern __shared__ float sm[];
    float* sA = sm;               // 64 x LDA
    float* sW = sm + 64 * LDA;    // 128 x LDA
    int tid = threadIdx.x;
    int wid = tid >> 5;
    int wm = wid & 1, wn = wid >> 1;       // 2 x 4 warp grid
    int r0 = blockIdx.x * 64;

    // load A tile (zero-padded rows) : 64x128 = 2048 float4
    #pragma unroll
    for (int i = 0; i < 8; i++) {
        int l = tid + i * 256;
        int row = l >> 5, q = l & 31;
        float4 v = make_float4(0.f, 0.f, 0.f, 0.f);
        int gr = r0 + row;
        if (gr < N_NODES) v = *(const float4*)(A + (size_t)gr * 128 + q * 4);
        *(float4*)(sA + row * LDA + q * 4) = v;
    }
    // load W : 128x128 = 4096 float4
    #pragma unroll
    for (int i = 0; i < 16; i++) {
        int l = tid + i * 256;
        int row = l >> 5, q = l & 31;
        *(float4*)(sW + row * LDA + q * 4) = *(const float4*)(W + (size_t)row * 128 + q * 4);
    }
    __syncthreads();

    wmma::fragment<wmma::accumulator, 16, 16, 8, float> acc[2][2];
    #pragma unroll
    for (int i = 0; i < 2; i++)
        #pragma unroll
        for (int j = 0; j < 2; j++)
            wmma::fill_fragment(acc[i][j], 0.f);

    #pragma unroll
    for (int k0 = 0; k0 < 128; k0 += 8) {
        wmma::fragment<wmma::matrix_a, 16, 16, 8, wmma::precision::tf32, wmma::row_major> af[2];
        wmma::fragment<wmma::matrix_b, 16, 16, 8, wmma::precision::tf32, wmma::row_major> bf[2];
        #pragma unroll
        for (int i = 0; i < 2; i++) {
            wmma::load_matrix_sync(af[i], sA + (wm * 32 + i * 16) * LDA + k0, LDA);
            #pragma unroll
            for (int t = 0; t < af[i].num_elements; t++)
                af[i].x[t] = wmma::__float_to_tf32(af[i].x[t]);
        }
        #pragma unroll
        for (int j = 0; j < 2; j++) {
            wmma::load_matrix_sync(bf[j], sW + k0 * LDA + wn * 32 + j * 16, LDA);
            #pragma unroll
            for (int t = 0; t < bf[j].num_elements; t++)
                bf[j].x[t] = wmma::__float_to_tf32(bf[j].x[t]);
        }
        #pragma unroll
        for (int i = 0; i < 2; i++)
            #pragma unroll
            for (int j = 0; j < 2; j++)
                wmma::mma_sync(acc[i][j], af[i], bf[j], acc[i][j]);
    }

    // epilogue via smem roundtrip (reuse sA as 64 x LDA)
    __syncthreads();
    #pragma unroll
    for (int i = 0; i < 2; i++)
        #pragma unroll
        for (int j = 0; j < 2; j++)
            wmma::store_matrix_sync(sA + (wm * 32 + i * 16) * LDA + wn * 32 + j * 16,
                                    acc[i][j], LDA, wmma::mem_row_major);
    __syncthreads();
    #pragma unroll
    for (int i = 0; i < 8; i++) {
        int l = tid + i * 256;
        int row = l >> 5, q = l & 31;
        int gr = r0 + row;
        if (gr >= N_NODES) continue;
        float s = g_dinv[gr];
        float4 v = *(float4*)(sA + row * LDA + q * 4);
        v.x *= s; v.y *= s; v.z *= s; v.w *= s;
        *(float4*)(g_y1 + (size_t)gr * 128 + q * 4) = v;
    }
}

// ---------------- GEMM 2 (tf32 WMMA): y2 = dinv .* (h @ W2), 128x70 ---------
// BM=64, BN=80 (5 n-tiles), 10 warps (2x5). W2 zero-padded to 80 cols.
#define LDW2 84
__global__ void __launch_bounds__(320) gemm2_k(const float* __restrict__ W2) {
    extern __shared__ float sm[];
    float* sH = sm;                // 64 x LDA
    float* sW = sm + 64 * LDA;     // 128 x LDW2
    int tid = threadIdx.x;
    int wid = tid >> 5;
    int wm = wid & 1, wn = wid >> 1;       // 2 x 5 warp grid
    int r0 = blockIdx.x * 64;

    // load H tile: 64x128 = 2048 float4, 320 threads
    for (int l = tid; l < 2048; l += 320) {
        int row = l >> 5, q = l & 31;
        float4 v = make_float4(0.f, 0.f, 0.f, 0.f);
        int gr = r0 + row;
        if (gr < N_NODES) v = *(const float4*)(g_h + (size_t)gr * 128 + q * 4);
        *(float4*)(sH + row * LDA + q * 4) = v;
    }
    // load W2: 128 x 80 (zero pad cols >= 70)
    for (int l = tid; l < 128 * 80; l += 320) {
        int row = l / 80, n = l % 80;
        sW[row * LDW2 + n] = (n < D_OUT) ? W2[(size_t)row * D_OUT + n] : 0.f;
    }
    __syncthreads();

    wmma::fragment<wmma::accumulator, 16, 16, 8, float> acc[2];
    wmma::fill_fragment(acc[0], 0.f);
    wmma::fill_fragment(acc[1], 0.f);

    #pragma unroll
    for (int k0 = 0; k0 < 128; k0 += 8) {
        wmma::fragment<wmma::matrix_a, 16, 16, 8, wmma::precision::tf32, wmma::row_major> af[2];
        wmma::fragment<wmma::matrix_b, 16, 16, 8, wmma::precision::tf32, wmma::row_major> bf;
        #pragma unroll
        for (int i = 0; i < 2; i++) {
            wmma::load_matrix_sync(af[i], sH + (wm * 32 + i * 16) * LDA + k0, LDA);
            #pragma unroll
            for (int t = 0; t < af[i].num_elements; t++)
                af[i].x[t] = wmma::__float_to_tf32(af[i].x[t]);
        }
        wmma::load_matrix_sync(bf, sW + k0 * LDW2 + wn * 16, LDW2);
        #pragma unroll
        for (int t = 0; t < bf.num_elements; t++)
            bf.x[t] = wmma::__float_to_tf32(bf.x[t]);
        wmma::mma_sync(acc[0], af[0], bf, acc[0]);
        wmma::mma_sync(acc[1], af[1], bf, acc[1]);
    }

    // epilogue: store to smem (64 x LDW2 region reusing sH), scale, write 72 cols
    __syncthreads();
    wmma::store_matrix_sync(sH + (wm * 32) * LDW2 + wn * 16, acc[0], LDW2, wmma::mem_row_major);
    wmma::store_matrix_sync(sH + (wm * 32 + 16) * LDW2 + wn * 16, acc[1], LDW2, wmma::mem_row_major);
    __syncthreads();
    for (int l = tid; l < 64 * 18; l += 320) {    // 64 rows x 18 float4 (72 cols)
        int row = l / 18, q = l % 18;
        int gr = r0 + row;
        if (gr >= N_NODES) continue;
        float s = g_dinv[gr];
        float4 v = *(float4*)(sH + row * LDW2 + q * 4);
        v.x *= s; v.y *= s; v.z *= s; v.w *= s;
        *(float4*)(g_y2 + (size_t)gr * D_OUT_P + q * 4) = v;
    }
}

// ---------------- gather 1: h = relu(dinv .* (Σ_nbr y1 + y1_self) + b1) -----
__global__ void __launch_bounds__(256) gather1_k(const float* __restrict__ b1) {
    int w = (blockIdx.x * 256 + threadIdx.x) >> 5;
    int lane = threadIdx.x & 31;
    if (w >= N_NODES) return;
    int start = g_rowptr[w], end = g_rowptr[w + 1];
    float4 a = *(const float4*)(g_y1 + (size_t)w * 128 + lane * 4);  // self loop
    for (int base = start; base < end; base += 32) {
        int idx = base + lane;
        int s = (idx < end) ? g_nbr[idx] : 0;
        int cnt = min(32, end - base);
        for (int j = 0; j < cnt; j++) {
            int sj = __shfl_sync(0xffffffffu, s, j);
            float4 v = *(const float4*)(g_y1 + (size_t)sj * 128 + lane * 4);
            a.x += v.x; a.y += v.y; a.z += v.z; a.w += v.w;
        }
    }
    float d = g_dinv[w];
    float4 bb = *(const float4*)(b1 + lane * 4);
    float4 h;
    h.x = fmaxf(0.f, fmaf(d, a.x, bb.x));
    h.y = fmaxf(0.f, fmaf(d, a.y, bb.y));
    h.z = fmaxf(0.f, fmaf(d, a.z, bb.z));
    h.w = fmaxf(0.f, fmaf(d, a.w, bb.w));
    *(float4*)(g_h + (size_t)w * 128 + lane * 4) = h;
}

// ---------------- gather 2: out = dinv .* (Σ_nbr y2 + y2_self) + b2 ---------
__global__ void __launch_bounds__(256) gather2_k(const float* __restrict__ b2,
                                                 float* __restrict__ out) {
    int w = (blockIdx.x * 256 + threadIdx.x) >> 5;
    int lane = threadIdx.x & 31;
    if (w >= N_NODES) return;
    int start = g_rowptr[w], end = g_rowptr[w + 1];
    float4 a = make_float4(0.f, 0.f, 0.f, 0.f);
    bool act = lane < 18;
    if (act) a = *(const float4*)(g_y2 + (size_t)w * D_OUT_P + lane * 4);
    for (int base = start; base < end; base += 32) {
        int idx = base + lane;
        int s = (idx < end) ? g_nbr[idx] : 0;
        int cnt = min(32, end - base);
        for (int j = 0; j < cnt; j++) {
            int sj = __shfl_sync(0xffffffffu, s, j);
            if (act) {
                float4 v = *(const float4*)(g_y2 + (size_t)sj * D_OUT_P + lane * 4);
                a.x += v.x; a.y += v.y; a.z += v.z; a.w += v.w;
            }
        }
    }
    if (act) {
        float d = g_dinv[w];
        int c = lane * 4;
        float* o = out + (size_t)w * D_OUT + c;
        float2 r0 = make_float2(fmaf(d, a.x, b2[c]), fmaf(d, a.y, b2[c + 1]));
        *(float2*)o = r0;
        if (lane < 17) {
            float2 r1 = make_float2(fmaf(d, a.z, b2[c + 2]), fmaf(d, a.w, b2[c + 3]));
            *(float2*)(o + 2) = r1;
        }
    }
}

// ---------------- launch -----------------------------------------------------
extern "C" void kernel_launch(void* const* d_in, const int* in_sizes, int n_in,
                              void* d_out, int out_size) {
    const float* x  = (const float*)d_in[0];
    const void*  ei = d_in[1];
    const float* W1 = (const float*)d_in[2];
    const float* b1 = (const float*)d_in[3];
    const float* W2 = (const float*)d_in[4];
    const float* b2 = (const float*)d_in[5];
    float* out = (float*)d_out;

    const int nscan = (N_NODES + 1023) / 1024;   // 98
    const int smem1 = (64 * LDA + 128 * LDA) * 4;      // 101376 B
    const int smem2 = (64 * LDA + 128 * LDW2) * 4;     //  76800 B
    static int attr_done = 0;
    if (!attr_done) {
        cudaFuncSetAttribute(gemm1_k, cudaFuncAttributeMaxDynamicSharedMemorySize, smem1);
        cudaFuncSetAttribute(gemm2_k, cudaFuncAttributeMaxDynamicSharedMemorySize, smem2);
        attr_done = 1;
    }

    detect_k<<<1, 32>>>(ei);
    zero_deg_k<<<(N_NODES + 255) / 256, 256>>>();
    count_k<<<(N_EDGES + 255) / 256, 256>>>(ei);
    dinv_k<<<(N_NODES + 255) / 256, 256>>>();

    scan1_k<<<nscan, 1024>>>();
    scan2_k<<<1, 128>>>(nscan);
    scan3_k<<<(N_NODES + 255) / 256, 256>>>();
    fill_k<<<(N_EDGES + 255) / 256, 256>>>(ei);

    gemm1_k<<<(N_NODES + 63) / 64, 256, smem1>>>(x, W1);
    gather1_k<<<(N_NODES * 32 + 255) / 256, 256>>>(b1);

    gemm2_k<<<(N_NODES + 63) / 64, 320, smem2>>>(W2);
    gather2_k<<<(N_NODES * 32 + 255) / 256, 256>>>(b2, out);
}

// round 4
// speedup vs baseline: 1.9853x; 1.0874x over previous
#include <cuda_runtime.h>
#include <cuda_fp16.h>
#include <mma.h>
#include <cstdint>

using namespace nvcuda;

#define N_NODES 100000
#define N_EDGES 1600000
#define D_IN    128
#define D_HID   128
#define D_OUT   70
#define D_OUT_P 72   // padded stride for layer-2 intermediates

// ---------------- scratch (static device memory; no allocation) -------------
__device__ __align__(256) int    g_deg   [N_NODES];
__device__ __align__(256) float  g_dinv  [N_NODES];
__device__ __align__(256) int    g_rowptr[N_NODES + 1];
__device__ __align__(256) int    g_cursor[N_NODES];
__device__ __align__(256) int    g_incl  [N_NODES];
__device__ __align__(256) int    g_bsum  [128];
__device__ __align__(256) int    g_boff  [128];
__device__ __align__(256) int    g_nbr   [N_EDGES];
__device__ __align__(256) __half g_y1    [(size_t)N_NODES * D_HID];
__device__ __align__(256) float  g_h     [(size_t)N_NODES * D_HID];
__device__ __align__(256) __half g_y2    [(size_t)N_NODES * D_OUT_P];
__device__ int g_is64;

// ---------------- edge-index width detection (int32 vs int64) ---------------
__device__ __forceinline__ int load_idx(const void* ei, long long i, int is64) {
    return is64 ? (int)(((const long long*)ei)[i]) : ((const int*)ei)[i];
}

// zero deg + detect index width (detect done by block 0 / thread 0)
__global__ void init_k(const void* ei) {
    int i = blockIdx.x * blockDim.x + threadIdx.x;
    if (i < N_NODES) g_deg[i] = 0;
    if (i == 0) {
        const int* p = (const int*)ei;
        int is64 = 1;
        for (int t = 0; t < 1000; t++) {
            if (p[2 * t + 1] != 0) { is64 = 0; break; }
        }
        g_is64 = is64;
    }
}

__global__ void count_k(const void* __restrict__ ei) {
    int e = blockIdx.x * blockDim.x + threadIdx.x;
    if (e >= N_EDGES) return;
    int dst = load_idx(ei, (long long)N_EDGES + e, g_is64);
    atomicAdd(&g_deg[dst], 1);
}

// ---------------- CSR build: hierarchical exclusive scan of deg --------------
__global__ void __launch_bounds__(1024) scan1_k() {
    __shared__ int s[1024];
    int t = threadIdx.x;
    int i = blockIdx.x * 1024 + t;
    s[t] = (i < N_NODES) ? g_deg[i] : 0;
    __syncthreads();
    #pragma unroll
    for (int off = 1; off < 1024; off <<= 1) {
        int v = (t >= off) ? s[t - off] : 0;
        __syncthreads();
        s[t] += v;
        __syncthreads();
    }
    if (i < N_NODES) g_incl[i] = s[t];
    if (t == 1023) g_bsum[blockIdx.x] = s[1023];
}

__global__ void __launch_bounds__(128) scan2_k(int nblocks) {
    __shared__ int s[128];
    int t = threadIdx.x;
    int v0 = (t < nblocks) ? g_bsum[t] : 0;
    s[t] = v0;
    __syncthreads();
    #pragma unroll
    for (int off = 1; off < 128; off <<= 1) {
        int v = (t >= off) ? s[t - off] : 0;
        __syncthreads();
        s[t] += v;
        __syncthreads();
    }
    if (t < nblocks) g_boff[t] = s[t] - v0;   // exclusive
}

// rowptr + cursors + dinv (fused)
__global__ void scan3_k() {
    int i = blockIdx.x * blockDim.x + threadIdx.x;
    if (i >= N_NODES) return;
    int deg = g_deg[i];
    int incl = g_incl[i] + g_boff[i >> 10];
    g_rowptr[i + 1] = incl;
    g_cursor[i] = incl - deg;
    g_dinv[i] = rsqrtf((float)(deg + 1));   // +1 self-loop
    if (i == 0) g_rowptr[0] = 0;
}

__global__ void fill_k(const void* __restrict__ ei) {
    int e = blockIdx.x * blockDim.x + threadIdx.x;
    if (e >= N_EDGES) return;
    int is64 = g_is64;
    int src = load_idx(ei, e, is64);
    int dst = load_idx(ei, (long long)N_EDGES + e, is64);
    int pos = atomicAdd(&g_cursor[dst], 1);
    g_nbr[pos] = src;
}

__device__ __forceinline__ uint2 pack_half4(float x, float y, float z, float w) {
    __half2 h0 = __floats2half2_rn(x, y);
    __half2 h1 = __floats2half2_rn(z, w);
    uint2 u;
    u.x = *(unsigned*)&h0;
    u.y = *(unsigned*)&h1;
    return u;
}

__device__ __forceinline__ void add_half4(float4& a, uint2 u) {
    float2 lo = __half22float2(*(__half2*)&u.x);
    float2 hi = __half22float2(*(__half2*)&u.y);
    a.x += lo.x; a.y += lo.y; a.z += hi.x; a.w += hi.y;
}

// ---------------- GEMM 1 (tf32 WMMA): y1 = dinv .* (x @ W1), 128x128 --------
// BM=64, BN=128, 8 warps (2x4). K=128 fully staged in smem, 1 sync.
#define LDA 132
__global__ void __launch_bounds__(256) gemm1_k(const float* __restrict__ A,
                                               const float* __restrict__ W) {
    extern __shared__ float sm[];
    float* sA = sm;               // 64 x LDA
    float* sW = sm + 64 * LDA;    // 128 x LDA
    int tid = threadIdx.x;
    int wid = tid >> 5;
    int wm = wid & 1, wn = wid >> 1;       // 2 x 4 warp grid
    int r0 = blockIdx.x * 64;

    #pragma unroll
    for (int i = 0; i < 8; i++) {
        int l = tid + i * 256;
        int row = l >> 5, q = l & 31;
        float4 v = make_float4(0.f, 0.f, 0.f, 0.f);
        int gr = r0 + row;
        if (gr < N_NODES) v = *(const float4*)(A + (size_t)gr * 128 + q * 4);
        *(float4*)(sA + row * LDA + q * 4) = v;
    }
    #pragma unroll
    for (int i = 0; i < 16; i++) {
        int l = tid + i * 256;
        int row = l >> 5, q = l & 31;
        *(float4*)(sW + row * LDA + q * 4) = *(const float4*)(W + (size_t)row * 128 + q * 4);
    }
    __syncthreads();

    wmma::fragment<wmma::accumulator, 16, 16, 8, float> acc[2][2];
    #pragma unroll
    for (int i = 0; i < 2; i++)
        #pragma unroll
        for (int j = 0; j < 2; j++)
            wmma::fill_fragment(acc[i][j], 0.f);

    #pragma unroll
    for (int k0 = 0; k0 < 128; k0 += 8) {
        wmma::fragment<wmma::matrix_a, 16, 16, 8, wmma::precision::tf32, wmma::row_major> af[2];
        wmma::fragment<wmma::matrix_b, 16, 16, 8, wmma::precision::tf32, wmma::row_major> bf[2];
        #pragma unroll
        for (int i = 0; i < 2; i++) {
            wmma::load_matrix_sync(af[i], sA + (wm * 32 + i * 16) * LDA + k0, LDA);
            #pragma unroll
            for (int t = 0; t < af[i].num_elements; t++)
                af[i].x[t] = wmma::__float_to_tf32(af[i].x[t]);
        }
        #pragma unroll
        for (int j = 0; j < 2; j++) {
            wmma::load_matrix_sync(bf[j], sW + k0 * LDA + wn * 32 + j * 16, LDA);
            #pragma unroll
            for (int t = 0; t < bf[j].num_elements; t++)
                bf[j].x[t] = wmma::__float_to_tf32(bf[j].x[t]);
        }
        #pragma unroll
        for (int i = 0; i < 2; i++)
            #pragma unroll
            for (int j = 0; j < 2; j++)
                wmma::mma_sync(acc[i][j], af[i], bf[j], acc[i][j]);
    }

    __syncthreads();
    #pragma unroll
    for (int i = 0; i < 2; i++)
        #pragma unroll
        for (int j = 0; j < 2; j++)
            wmma::store_matrix_sync(sA + (wm * 32 + i * 16) * LDA + wn * 32 + j * 16,
                                    acc[i][j], LDA, wmma::mem_row_major);
    __syncthreads();
    #pragma unroll
    for (int i = 0; i < 8; i++) {
        int l = tid + i * 256;
        int row = l >> 5, q = l & 31;
        int gr = r0 + row;
        if (gr >= N_NODES) continue;
        float s = g_dinv[gr];
        float4 v = *(float4*)(sA + row * LDA + q * 4);
        *(uint2*)(g_y1 + (size_t)gr * 128 + q * 4) =
            pack_half4(v.x * s, v.y * s, v.z * s, v.w * s);
    }
}

// ---------------- GEMM 2 (tf32 WMMA): y2 = dinv .* (h @ W2), 128x70 ---------
#define LDW2 84
__global__ void __launch_bounds__(320) gemm2_k(const float* __restrict__ W2) {
    extern __shared__ float sm[];
    float* sH = sm;                // 64 x LDA
    float* sW = sm + 64 * LDA;     // 128 x LDW2
    int tid = threadIdx.x;
    int wid = tid >> 5;
    int wm = wid & 1, wn = wid >> 1;       // 2 x 5 warp grid
    int r0 = blockIdx.x * 64;

    for (int l = tid; l < 2048; l += 320) {
        int row = l >> 5, q = l & 31;
        float4 v = make_float4(0.f, 0.f, 0.f, 0.f);
        int gr = r0 + row;
        if (gr < N_NODES) v = *(const float4*)(g_h + (size_t)gr * 128 + q * 4);
        *(float4*)(sH + row * LDA + q * 4) = v;
    }
    for (int l = tid; l < 128 * 80; l += 320) {
        int row = l / 80, n = l % 80;
        sW[row * LDW2 + n] = (n < D_OUT) ? W2[(size_t)row * D_OUT + n] : 0.f;
    }
    __syncthreads();

    wmma::fragment<wmma::accumulator, 16, 16, 8, float> acc[2];
    wmma::fill_fragment(acc[0], 0.f);
    wmma::fill_fragment(acc[1], 0.f);

    #pragma unroll
    for (int k0 = 0; k0 < 128; k0 += 8) {
        wmma::fragment<wmma::matrix_a, 16, 16, 8, wmma::precision::tf32, wmma::row_major> af[2];
        wmma::fragment<wmma::matrix_b, 16, 16, 8, wmma::precision::tf32, wmma::row_major> bf;
        #pragma unroll
        for (int i = 0; i < 2; i++) {
            wmma::load_matrix_sync(af[i], sH + (wm * 32 + i * 16) * LDA + k0, LDA);
            #pragma unroll
            for (int t = 0; t < af[i].num_elements; t++)
                af[i].x[t] = wmma::__float_to_tf32(af[i].x[t]);
        }
        wmma::load_matrix_sync(bf, sW + k0 * LDW2 + wn * 16, LDW2);
        #pragma unroll
        for (int t = 0; t < bf.num_elements; t++)
            bf.x[t] = wmma::__float_to_tf32(bf.x[t]);
        wmma::mma_sync(acc[0], af[0], bf, acc[0]);
        wmma::mma_sync(acc[1], af[1], bf, acc[1]);
    }

    __syncthreads();
    wmma::store_matrix_sync(sH + (wm * 32) * LDW2 + wn * 16, acc[0], LDW2, wmma::mem_row_major);
    wmma::store_matrix_sync(sH + (wm * 32 + 16) * LDW2 + wn * 16, acc[1], LDW2, wmma::mem_row_major);
    __syncthreads();
    for (int l = tid; l < 64 * 18; l += 320) {    // 64 rows x 18 half4 groups (72 cols)
        int row = l / 18, q = l % 18;
        int gr = r0 + row;
        if (gr >= N_NODES) continue;
        float s = g_dinv[gr];
        float4 v = *(float4*)(sH + row * LDW2 + q * 4);
        *(uint2*)(g_y2 + (size_t)gr * D_OUT_P + q * 4) =
            pack_half4(v.x * s, v.y * s, v.z * s, v.w * s);
    }
}

// ---------------- gather 1: h = relu(dinv .* (Σ_nbr y1 + y1_self) + b1) -----
// one warp per node; lane l owns columns [4l, 4l+4); fp16 messages, fp32 acc
__global__ void __launch_bounds__(256) gather1_k(const float* __restrict__ b1) {
    int w = (blockIdx.x * 256 + threadIdx.x) >> 5;
    int lane = threadIdx.x & 31;
    if (w >= N_NODES) return;
    int start = g_rowptr[w], end = g_rowptr[w + 1];
    float4 a = make_float4(0.f, 0.f, 0.f, 0.f);
    add_half4(a, *(const uint2*)(g_y1 + (size_t)w * 128 + lane * 4));  // self loop
    for (int base = start; base < end; base += 32) {
        int idx = base + lane;
        int s = (idx < end) ? g_nbr[idx] : 0;
        int cnt = min(32, end - base);
        for (int j = 0; j < cnt; j++) {
            int sj = __shfl_sync(0xffffffffu, s, j);
            add_half4(a, *(const uint2*)(g_y1 + (size_t)sj * 128 + lane * 4));
        }
    }
    float d = g_dinv[w];
    float4 bb = *(const float4*)(b1 + lane * 4);
    float4 h;
    h.x = fmaxf(0.f, fmaf(d, a.x, bb.x));
    h.y = fmaxf(0.f, fmaf(d, a.y, bb.y));
    h.z = fmaxf(0.f, fmaf(d, a.z, bb.z));
    h.w = fmaxf(0.f, fmaf(d, a.w, bb.w));
    *(float4*)(g_h + (size_t)w * 128 + lane * 4) = h;
}

// ---------------- gather 2: out = dinv .* (Σ_nbr y2 + y2_self) + b2 ---------
__global__ void __launch_bounds__(256) gather2_k(const float* __restrict__ b2,
                                                 float* __restrict__ out) {
    int w = (blockIdx.x * 256 + threadIdx.x) >> 5;
    int lane = threadIdx.x & 31;
    if (w >= N_NODES) return;
    int start = g_rowptr[w], end = g_rowptr[w + 1];
    float4 a = make_float4(0.f, 0.f, 0.f, 0.f);
    bool act = lane < 18;
    if (act) add_half4(a, *(const uint2*)(g_y2 + (size_t)w * D_OUT_P + lane * 4));
    for (int base = start; base < end; base += 32) {
        int idx = base + lane;
        int s = (idx < end) ? g_nbr[idx] : 0;
        int cnt = min(32, end - base);
        for (int j = 0; j < cnt; j++) {
            int sj = __shfl_sync(0xffffffffu, s, j);
            if (act) add_half4(a, *(const uint2*)(g_y2 + (size_t)sj * D_OUT_P + lane * 4));
        }
    }
    if (act) {
        float d = g_dinv[w];
        int c = lane * 4;
        float* o = out + (size_t)w * D_OUT + c;
        float2 r0 = make_float2(fmaf(d, a.x, b2[c]), fmaf(d, a.y, b2[c + 1]));
        *(float2*)o = r0;
        if (lane < 17) {
            float2 r1 = make_float2(fmaf(d, a.z, b2[c + 2]), fmaf(d, a.w, b2[c + 3]));
            *(float2*)(o + 2) = r1;
        }
    }
}

// ---------------- launch -----------------------------------------------------
extern "C" void kernel_launch(void* const* d_in, const int* in_sizes, int n_in,
                              void* d_out, int out_size) {
    const float* x  = (const float*)d_in[0];
    const void*  ei = d_in[1];
    const float* W1 = (const float*)d_in[2];
    const float* b1 = (const float*)d_in[3];
    const float* W2 = (const float*)d_in[4];
    const float* b2 = (const float*)d_in[5];
    float* out = (float*)d_out;

    const int nscan = (N_NODES + 1023) / 1024;   // 98
    const int smem1 = (64 * LDA + 128 * LDA) * 4;      // 101376 B
    const int smem2 = (64 * LDA + 128 * LDW2) * 4;     //  76800 B
    cudaFuncSetAttribute(gemm1_k, cudaFuncAttributeMaxDynamicSharedMemorySize, smem1);
    cudaFuncSetAttribute(gemm2_k, cudaFuncAttributeMaxDynamicSharedMemorySize, smem2);

    init_k<<<(N_NODES + 255) / 256, 256>>>(ei);
    count_k<<<(N_EDGES + 255) / 256, 256>>>(ei);

    scan1_k<<<nscan, 1024>>>();
    scan2_k<<<1, 128>>>(nscan);
    scan3_k<<<(N_NODES + 255) / 256, 256>>>();
    fill_k<<<(N_EDGES + 255) / 256, 256>>>(ei);

    gemm1_k<<<(N_NODES + 63) / 64, 256, smem1>>>(x, W1);
    gather1_k<<<(N_NODES * 32 + 255) / 256, 256>>>(b1);

    gemm2_k<<<(N_NODES + 63) / 64, 320, smem2>>>(W2);
    gather2_k<<<(N_NODES * 32 + 255) / 256, 256>>>(b2, out);
}